// round 1
// baseline (speedup 1.0000x reference)
#include <cuda_runtime.h>

// VectorQuantizer: N=262144 points (D=64), K=1024 codes.
// out = [ z_q (N*64 floats) | encoding_inds as float (N) ]
//
// Score replicates the reference rounding exactly:
//   dist2[k] = fl( fl(ze_sq - 2*dot_k) + cb_sq[k] ),  argmin with first-index tie-break.
// fp32 throughput doubled via packed fma.rn.f32x2 (FFMA2): codebook staged in
// SMEM pair-interleaved (codes 2p,2p+1 as f32x2 per dim); z duplicated into
// (z_i,z_i) b64 registers once per point.

#define KCODES 1024
#define DIM    64
#define CHUNK  512   // codes per SMEM stage (2 stages)
#define TPB    256

#define SMEM_FLOATS (CHUNK * DIM + CHUNK)           // pair-interleaved codes + cb_sq
#define SMEM_BYTES  (SMEM_FLOATS * 4)               // 133120 B

__device__ float g_cbsq[KCODES];

static __device__ __forceinline__ unsigned long long pack2(float lo, float hi) {
    unsigned long long r;
    asm("mov.b64 %0, {%1, %2};" : "=l"(r)
        : "r"(__float_as_uint(lo)), "r"(__float_as_uint(hi)));
    return r;
}
static __device__ __forceinline__ void unpack2(unsigned long long v, float& lo, float& hi) {
    unsigned int a, b;
    asm("mov.b64 {%0, %1}, %2;" : "=r"(a), "=r"(b) : "l"(v));
    lo = __uint_as_float(a);
    hi = __uint_as_float(b);
}
static __device__ __forceinline__ unsigned long long fma2(unsigned long long a,
                                                          unsigned long long b,
                                                          unsigned long long c) {
    unsigned long long d;
    asm("fma.rn.f32x2 %0, %1, %2, %3;" : "=l"(d) : "l"(a), "l"(b), "l"(c));
    return d;
}
static __device__ __forceinline__ unsigned long long add2(unsigned long long a,
                                                          unsigned long long b) {
    unsigned long long d;
    asm("add.rn.f32x2 %0, %1, %2;" : "=l"(d) : "l"(a), "l"(b));
    return d;
}

// ---------------------------------------------------------------------------
// cb_sq[k] = sequential fp32 sum of squares of codebook row k.
__global__ void cbsq_kernel(const float* __restrict__ cb) {
    int k = blockIdx.x * blockDim.x + threadIdx.x;
    if (k < KCODES) {
        const float* r = cb + (size_t)k * DIM;
        float s = 0.f;
#pragma unroll
        for (int i = 0; i < DIM; i++)
            s = __fadd_rn(s, __fmul_rn(r[i], r[i]));
        g_cbsq[k] = s;
    }
}

// ---------------------------------------------------------------------------
__global__ __launch_bounds__(TPB, 1)
void vq_kernel(const float* __restrict__ z_e,
               const float* __restrict__ cb,
               float* __restrict__ out,
               int N) {
    extern __shared__ float smem[];
    float* s_cb  = smem;                 // CHUNK*DIM floats, pair-interleaved
    float* s_csq = smem + CHUNK * DIM;   // CHUNK floats (natural order)

    const int n = blockIdx.x * TPB + threadIdx.x;
    const bool active = (n < N);

    // Load z, build duplicated-pair registers, and ze_sq (sequential fp32 sum).
    unsigned long long zdup[DIM];
    float zsq = 0.f;
    if (active) {
        const float4* z4 = (const float4*)(z_e + (size_t)n * DIM);
#pragma unroll
        for (int i = 0; i < DIM / 4; i++) {
            float4 v = z4[i];
            zsq = __fadd_rn(zsq, __fmul_rn(v.x, v.x));
            zsq = __fadd_rn(zsq, __fmul_rn(v.y, v.y));
            zsq = __fadd_rn(zsq, __fmul_rn(v.z, v.z));
            zsq = __fadd_rn(zsq, __fmul_rn(v.w, v.w));
            zdup[4 * i + 0] = pack2(v.x, v.x);
            zdup[4 * i + 1] = pack2(v.y, v.y);
            zdup[4 * i + 2] = pack2(v.z, v.z);
            zdup[4 * i + 3] = pack2(v.w, v.w);
        }
    } else {
#pragma unroll
        for (int i = 0; i < DIM; i++) zdup[i] = 0ull;
    }

    float best = 3.4e38f;
    int   bidx = 0;

    for (int c0 = 0; c0 < KCODES; c0 += CHUNK) {
        __syncthreads();  // protect previous stage's SMEM reads

        // Cooperative stage: pair-interleave codes [c0, c0+CHUNK).
        const float4* src = (const float4*)(cb + (size_t)c0 * DIM);
        for (int e = threadIdx.x; e < CHUNK * DIM / 4; e += TPB) {
            float4 v  = src[e];
            int off   = e * 4;
            int k     = off >> 6;          // local code index
            int i     = off & (DIM - 1);   // dim
            int pair  = k >> 1;
            int half  = k & 1;
            float* dst = s_cb + (((pair << 6) + i) << 1) + half;
            dst[0] = v.x; dst[2] = v.y; dst[4] = v.z; dst[6] = v.w;
        }
        for (int e = threadIdx.x; e < CHUNK; e += TPB)
            s_csq[e] = g_cbsq[c0 + e];
        __syncthreads();

#pragma unroll 1
        for (int p = 0; p < CHUNK / 2; ++p) {
            const ulonglong2* row = (const ulonglong2*)(s_cb + (p << 7));  // p*64 float2
            unsigned long long a0 = 0ull, a1 = 0ull, a2 = 0ull, a3 = 0ull;
#pragma unroll
            for (int i = 0; i < DIM; i += 4) {
                ulonglong2 v01 = row[(i >> 1) + 0];
                ulonglong2 v23 = row[(i >> 1) + 1];
                a0 = fma2(zdup[i + 0], v01.x, a0);
                a1 = fma2(zdup[i + 1], v01.y, a1);
                a2 = fma2(zdup[i + 2], v23.x, a2);
                a3 = fma2(zdup[i + 3], v23.y, a3);
            }
            a0 = add2(a0, a2);
            a1 = add2(a1, a3);
            a0 = add2(a0, a1);

            float d0, d1;
            unpack2(a0, d0, d1);
            float cs0 = s_csq[2 * p];
            float cs1 = s_csq[2 * p + 1];

            // fl(zsq - 2*d) in one rounding (2*d exact), then fl(+cb_sq) —
            // exactly the reference's rounding sequence.
            float t0 = __fmaf_rn(-2.f, d0, zsq);
            float dist0 = __fadd_rn(t0, cs0);
            float t1 = __fmaf_rn(-2.f, d1, zsq);
            float dist1 = __fadd_rn(t1, cs1);

            int k0 = c0 + (p << 1);
            if (dist0 < best) { best = dist0; bidx = k0; }
            if (dist1 < best) { best = dist1; bidx = k0 + 1; }
        }
    }

    if (active) {
        // z_q = codebook[bidx] (bitwise-exact gather)
        float4* oq = (float4*)(out + (size_t)n * DIM);
        const float4* qr = (const float4*)(cb + (size_t)bidx * DIM);
#pragma unroll
        for (int i = 0; i < DIM / 4; i++) oq[i] = qr[i];
        // indices appended after z_q, cast to float (exact for k<2^24)
        out[(size_t)N * DIM + n] = (float)bidx;
    }
}

// ---------------------------------------------------------------------------
extern "C" void kernel_launch(void* const* d_in, const int* in_sizes, int n_in,
                              void* d_out, int out_size) {
    const float* z_e = (const float*)d_in[0];
    const float* cb  = (const float*)d_in[1];
    float* out = (float*)d_out;
    const int N = in_sizes[0] / DIM;

    cbsq_kernel<<<(KCODES + 255) / 256, 256>>>(cb);

    cudaFuncSetAttribute(vq_kernel, cudaFuncAttributeMaxDynamicSharedMemorySize,
                         SMEM_BYTES);
    const int grid = (N + TPB - 1) / TPB;
    vq_kernel<<<grid, TPB, SMEM_BYTES>>>(z_e, cb, out, N);
}